// round 11
// baseline (speedup 1.0000x reference)
#include <cuda_runtime.h>

#define TT 512
#define BB 512
#define DD 16
#define HH 64
#define BK 32          // timesteps per staged x block
#define NBK (TT / BK)
#define XRB (BK * DD * 4)   // bytes of x per (row, block) = 2048

typedef unsigned long long ull;

__device__ __forceinline__ ull fma2(ull a, ull b, ull c) {
    ull d;
    asm("fma.rn.f32x2 %0, %1, %2, %3;" : "=l"(d) : "l"(a), "l"(b), "l"(c));
    return d;
}
__device__ __forceinline__ ull addf2(ull a, ull b) {
    ull d;
    asm("add.rn.f32x2 %0, %1, %2;" : "=l"(d) : "l"(a), "l"(b));
    return d;
}
__device__ __forceinline__ float hadd2(ull a) {
    return __uint_as_float((unsigned)a) + __uint_as_float((unsigned)(a >> 32));
}
__device__ __forceinline__ float tanha(float x) {
    float y;
    asm("tanh.approx.f32 %0, %1;" : "=f"(y) : "f"(x));
    return y;
}
__device__ __forceinline__ float siga(float x) {
    return fmaf(0.5f, tanha(0.5f * x), 0.5f);
}
__device__ __forceinline__ void cpa16(unsigned smem, const void* gmem) {
    asm volatile("cp.async.ca.shared.global [%0], [%1], 16;\n"
                 :: "r"(smem), "l"(gmem));
}
__device__ __forceinline__ void cpa_commit() {
    asm volatile("cp.async.commit_group;\n" ::: "memory");
}
__device__ __forceinline__ void cpa_wait1() {
    asm volatile("cp.async.wait_group 1;\n" ::: "memory");
}
__device__ __forceinline__ void barpair(int id) {  // named barrier, 64 threads
    asm volatile("bar.sync %0, 64;" :: "r"(id) : "memory");
}

// ---------------------------------------------------------------------------
// Fused BiGRU kernel. Grid 128 (1 CTA/SM), CTA = 128 threads = 4 rows.
// Warp-pair p owns rows 2p, 2p+1 interleaved in-thread; pair-private staging
// of raw x (cp.async) and pair-private named barrier. Thread owns one unit:
// full w_hh rows (192 regs) + w_ih rows (48 regs); input projection computed
// in-loop (seeds the r/z accumulator chains; n-gate x-part kept separate).
// launch_bounds(128,1): registers free up to 512 — no spill pressure.
// ---------------------------------------------------------------------------
__global__ __launch_bounds__(128, 1)
void bigru_fused_kernel(const float* __restrict__ x,
                        const float* __restrict__ w_ih,
                        const float* __restrict__ w_hh,
                        const float* __restrict__ b_ih,
                        const float* __restrict__ b_hh,
                        const float* __restrict__ w_ih_b,
                        const float* __restrict__ b_ih_b,
                        const float* __restrict__ b_hh_b,
                        const float* __restrict__ fc_w,
                        const float* __restrict__ fc_b,
                        float* __restrict__ out)
{
    __shared__ __align__(16) float h_sh[2][4][HH];        // [parity][row][unit]
    __shared__ __align__(16) float xs[2][4][BK][DD];      // [buf][row][t][d] 16KB
    __shared__ float red_sh[4][HH];

    const int tid  = threadIdx.x;
    const int pair = tid >> 6;       // 0/1 ; rows 2*pair, 2*pair+1
    const int u    = tid & 63;
    const int rA   = 2 * pair, rB = 2 * pair + 1;
    const int b0   = blockIdx.x * 4;

    // recurrent weights: rows r(u), z(u), n(u) of w_hh — 48 ulonglong2
    ulonglong2 w[3][16];
    {
        const int rows[3] = { u, HH + u, 2 * HH + u };
        #pragma unroll
        for (int i = 0; i < 3; i++) {
            const ulonglong2* p = (const ulonglong2*)(w_hh + rows[i] * HH);
            #pragma unroll
            for (int j = 0; j < 16; j++) w[i][j] = p[j];
        }
    }
    // input weights: rows r(u), z(u), n(u) of w_ih — 12 ulonglong2
    ulonglong2 wi[3][4];
    {
        const int rows[3] = { u, HH + u, 2 * HH + u };
        #pragma unroll
        for (int i = 0; i < 3; i++) {
            const ulonglong2* p = (const ulonglong2*)(w_ih + rows[i] * DD);
            #pragma unroll
            for (int j = 0; j < 4; j++) wi[i][j] = p[j];
        }
    }
    const float br  = b_ih[u]          + b_hh[u];
    const float bz  = b_ih[HH + u]     + b_hh[HH + u];
    const float bni = b_ih[2 * HH + u];
    const float bhn = b_hh[2 * HH + u];

    const char* xgA = (const char*)(x + (size_t)(b0 + rA) * TT * DD);
    const char* xgB = (const char*)(x + (size_t)(b0 + rB) * TT * DD);
    const unsigned sA = (unsigned)__cvta_generic_to_shared(&xs[0][rA][0][0]);
    const unsigned sB = (unsigned)__cvta_generic_to_shared(&xs[0][rB][0][0]);
    const unsigned BUFSTRIDE = 4 * XRB;    // xs[1] - xs[0] = 8192 B

    float holdA = 0.f, holdB = 0.f;
    h_sh[0][rA][u] = 0.f;
    h_sh[0][rB][u] = 0.f;

    // prologue: stage x block 0 (2048 B per row = 128 chunks; 2 per thread)
    #pragma unroll
    for (int c = 0; c < 2; c++) {
        cpa16(sA + (u + 64 * c) * 16, xgA + (u + 64 * c) * 16);
        cpa16(sB + (u + 64 * c) * 16, xgB + (u + 64 * c) * 16);
    }
    cpa_commit();
    barpair(1 + pair);

    int p = 0;
    for (int blk = 0; blk < NBK; ++blk) {
        if (blk + 1 < NBK) {
            unsigned off = (blk & 1) ? 0u : BUFSTRIDE;
            const char* gA = xgA + (size_t)(blk + 1) * XRB;
            const char* gB = xgB + (size_t)(blk + 1) * XRB;
            #pragma unroll
            for (int c = 0; c < 2; c++) {
                cpa16(sA + off + (u + 64 * c) * 16, gA + (u + 64 * c) * 16);
                cpa16(sB + off + (u + 64 * c) * 16, gB + (u + 64 * c) * 16);
            }
        }
        cpa_commit();
        cpa_wait1();
        barpair(1 + pair);

        const ulonglong2* xbA = (const ulonglong2*)&xs[blk & 1][rA][0][0];
        const ulonglong2* xbB = (const ulonglong2*)&xs[blk & 1][rB][0][0];

        #pragma unroll 2
        for (int tt = 0; tt < BK; ++tt) {
            // ---------- row A: input projection seeds + recurrent dots ------
            ull a0, a1, an;              // r/z chains (seeded by x-proj), n x-part
            ull h0b, h1b, h2a, h2b;      // second halves + n h-chains
            {
                a0 = 0ull; a1 = 0ull; an = 0ull;
                #pragma unroll
                for (int j = 0; j < 4; j++) {
                    ulonglong2 xv = xbA[tt * 4 + j];     // 4 floats of x
                    a0 = fma2(wi[0][j].x, xv.x, a0);
                    a0 = fma2(wi[0][j].y, xv.y, a0);
                    a1 = fma2(wi[1][j].x, xv.x, a1);
                    a1 = fma2(wi[1][j].y, xv.y, a1);
                    an = fma2(wi[2][j].x, xv.x, an);
                    an = fma2(wi[2][j].y, xv.y, an);
                }
                const ulonglong2* hp = (const ulonglong2*)&h_sh[p][rA][0];
                h0b = 0ull; h1b = 0ull; h2a = 0ull; h2b = 0ull;
                #pragma unroll
                for (int j = 0; j < 8; j++) {
                    ulonglong2 hv = hp[j];
                    a0  = fma2(w[0][j].x, hv.x, a0);  a0  = fma2(w[0][j].y, hv.y, a0);
                    a1  = fma2(w[1][j].x, hv.x, a1);  a1  = fma2(w[1][j].y, hv.y, a1);
                    h2a = fma2(w[2][j].x, hv.x, h2a); h2a = fma2(w[2][j].y, hv.y, h2a);
                }
                #pragma unroll
                for (int j = 8; j < 16; j++) {
                    ulonglong2 hv = hp[j];
                    h0b = fma2(w[0][j].x, hv.x, h0b); h0b = fma2(w[0][j].y, hv.y, h0b);
                    h1b = fma2(w[1][j].x, hv.x, h1b); h1b = fma2(w[1][j].y, hv.y, h1b);
                    h2b = fma2(w[2][j].x, hv.x, h2b); h2b = fma2(w[2][j].y, hv.y, h2b);
                }
            }

            // ---------- row B: same, issues while A's chains resolve --------
            ull d0, d1, dn, k0b, k1b, k2a, k2b;
            {
                d0 = 0ull; d1 = 0ull; dn = 0ull;
                #pragma unroll
                for (int j = 0; j < 4; j++) {
                    ulonglong2 xv = xbB[tt * 4 + j];
                    d0 = fma2(wi[0][j].x, xv.x, d0);
                    d0 = fma2(wi[0][j].y, xv.y, d0);
                    d1 = fma2(wi[1][j].x, xv.x, d1);
                    d1 = fma2(wi[1][j].y, xv.y, d1);
                    dn = fma2(wi[2][j].x, xv.x, dn);
                    dn = fma2(wi[2][j].y, xv.y, dn);
                }
                const ulonglong2* hp = (const ulonglong2*)&h_sh[p][rB][0];
                k0b = 0ull; k1b = 0ull; k2a = 0ull; k2b = 0ull;
                #pragma unroll
                for (int j = 0; j < 8; j++) {
                    ulonglong2 hv = hp[j];
                    d0  = fma2(w[0][j].x, hv.x, d0);  d0  = fma2(w[0][j].y, hv.y, d0);
                    d1  = fma2(w[1][j].x, hv.x, d1);  d1  = fma2(w[1][j].y, hv.y, d1);
                    k2a = fma2(w[2][j].x, hv.x, k2a); k2a = fma2(w[2][j].y, hv.y, k2a);
                }
                #pragma unroll
                for (int j = 8; j < 16; j++) {
                    ulonglong2 hv = hp[j];
                    k0b = fma2(w[0][j].x, hv.x, k0b); k0b = fma2(w[0][j].y, hv.y, k0b);
                    k1b = fma2(w[1][j].x, hv.x, k1b); k1b = fma2(w[1][j].y, hv.y, k1b);
                    k2b = fma2(w[2][j].x, hv.x, k2b); k2b = fma2(w[2][j].y, hv.y, k2b);
                }
            }

            // ---------- finalize A ----------
            {
                float rr = siga(hadd2(addf2(a0, h0b)) + br);
                float zz = siga(hadd2(addf2(a1, h1b)) + bz);
                float nn = tanha(fmaf(rr, hadd2(addf2(h2a, h2b)) + bhn,
                                      hadd2(an) + bni));
                holdA = fmaf(zz, holdA - nn, nn);
                h_sh[p ^ 1][rA][u] = holdA;
            }
            // ---------- finalize B ----------
            {
                float rr = siga(hadd2(addf2(d0, k0b)) + br);
                float zz = siga(hadd2(addf2(d1, k1b)) + bz);
                float nn = tanha(fmaf(rr, hadd2(addf2(k2a, k2b)) + bhn,
                                      hadd2(dn) + bni));
                holdB = fmaf(zz, holdB - nn, nn);
                h_sh[p ^ 1][rB][u] = holdB;
            }
            barpair(1 + pair);
            p ^= 1;
        }
    }
    __syncthreads();

    // ---- epilogue: backward GRU = ONE step from h=0 on x[:,T-1,:]; then fc ----
    #pragma unroll
    for (int k = 0; k < 2; k++) {
        const int r = 2 * pair + k;
        const int b = b0 + r;
        const float hold = k ? holdB : holdA;
        const int j = u;
        const float* xl = x + ((size_t)b * TT + (TT - 1)) * DD;
        float xv[DD];
        #pragma unroll
        for (int kk = 0; kk < DD; kk++) xv[kk] = __ldg(xl + kk);

        float ar  = __ldg(b_ih_b + j)          + __ldg(b_hh_b + j);
        float az  = __ldg(b_ih_b + HH + j)     + __ldg(b_hh_b + HH + j);
        float anx = __ldg(b_ih_b + 2 * HH + j);
        float anh = __ldg(b_hh_b + 2 * HH + j);
        const float* wr = w_ih_b + (size_t)j * DD;
        const float* wz = w_ih_b + (size_t)(HH + j) * DD;
        const float* wn = w_ih_b + (size_t)(2 * HH + j) * DD;
        #pragma unroll
        for (int kk = 0; kk < DD; kk++) {
            ar  += __ldg(wr + kk) * xv[kk];
            az  += __ldg(wz + kk) * xv[kk];
            anx += __ldg(wn + kk) * xv[kk];
        }
        float rb = siga(ar);
        float zb = siga(az);
        float nb = tanha(anx + rb * anh);
        float hb = (1.f - zb) * nb;            // h_prev = 0

        red_sh[r][j] = hold * __ldg(fc_w + j) + hb * __ldg(fc_w + HH + j);
    }
    __syncthreads();
    if (tid < 4) {
        float sum = __ldg(fc_b);
        #pragma unroll
        for (int k = 0; k < HH; k++) sum += red_sh[tid][k];
        out[b0 + tid] = sum;
    }
}

extern "C" void kernel_launch(void* const* d_in, const int* in_sizes, int n_in,
                              void* d_out, int out_size)
{
    const float* x      = (const float*)d_in[0];
    const float* w_ih_f = (const float*)d_in[1];
    const float* w_hh_f = (const float*)d_in[2];
    const float* b_ih_f = (const float*)d_in[3];
    const float* b_hh_f = (const float*)d_in[4];
    const float* w_ih_b = (const float*)d_in[5];
    /* d_in[6] = w_hh_b unused: backward direction starts from h=0 */
    const float* b_ih_b = (const float*)d_in[7];
    const float* b_hh_b = (const float*)d_in[8];
    const float* fc_w   = (const float*)d_in[9];
    const float* fc_b   = (const float*)d_in[10];

    bigru_fused_kernel<<<BB / 4, 128>>>(x, w_ih_f, w_hh_f, b_ih_f, b_hh_f,
                                        w_ih_b, b_ih_b, b_hh_b,
                                        fc_w, fc_b, (float*)d_out);
}

// round 12
// speedup vs baseline: 1.6010x; 1.6010x over previous
#include <cuda_runtime.h>
#include <cuda_fp16.h>

#define TT 512
#define BB 512
#define DD 16
#define HH 64
#define PT 64          // timesteps per precompute CTA
#define BK 16          // timesteps per staged xg block in rec kernel
#define NBK (TT / BK)
#define XGBB (BK * 256 * 2)   // bytes per staged block = 8192

typedef unsigned long long ull;

__device__ __forceinline__ ull fma2(ull a, ull b, ull c) {
    ull d;
    asm("fma.rn.f32x2 %0, %1, %2, %3;" : "=l"(d) : "l"(a), "l"(b), "l"(c));
    return d;
}
__device__ __forceinline__ ull addf2(ull a, ull b) {
    ull d;
    asm("add.rn.f32x2 %0, %1, %2;" : "=l"(d) : "l"(a), "l"(b));
    return d;
}
__device__ __forceinline__ float hadd2(ull a) {
    return __uint_as_float((unsigned)a) + __uint_as_float((unsigned)(a >> 32));
}
__device__ __forceinline__ float tanha(float x) {
    float y;
    asm("tanh.approx.f32 %0, %1;" : "=f"(y) : "f"(x));
    return y;
}
__device__ __forceinline__ float siga(float x) {
    return fmaf(0.5f, tanha(0.5f * x), 0.5f);
}
__device__ __forceinline__ void cpa16(unsigned smem, const void* gmem) {
    asm volatile("cp.async.ca.shared.global [%0], [%1], 16;\n"
                 :: "r"(smem), "l"(gmem));
}
__device__ __forceinline__ void cpa_commit() {
    asm volatile("cp.async.commit_group;\n" ::: "memory");
}
__device__ __forceinline__ void cpa_wait1() {
    asm volatile("cp.async.wait_group 1;\n" ::: "memory");
}
__device__ __forceinline__ void bargrp(int id) {   // named barrier, 64 threads
    asm volatile("bar.sync %0, 64;" :: "r"(id) : "memory");
}

// scratch: xg[b][t][u][{r,z,n,pad}] fp16; r,z include b_ih+b_hh, n includes b_ih
__device__ __half g_xg[(size_t)BB * TT * 256];

// ---------------------------------------------------------------------------
// Kernel 1: xg precompute (proven in R10). thread = (unit u, t-half); all 3
// gates per unit; packed {r,z,n,0} 8-byte store.
// ---------------------------------------------------------------------------
__global__ __launch_bounds__(128)
void xg_kernel(const float* __restrict__ x,
               const float* __restrict__ w_ih,
               const float* __restrict__ b_ih,
               const float* __restrict__ b_hh)
{
    __shared__ __align__(16) float xs[PT][DD];
    const int tid = threadIdx.x;
    const int u   = tid & 63;
    const int th  = tid >> 6;
    const int b   = blockIdx.y;
    const int t0  = blockIdx.x * PT;

    ulonglong2 wv[3][DD / 4];
    {
        const int rows[3] = { u, HH + u, 2 * HH + u };
        #pragma unroll
        for (int g = 0; g < 3; g++) {
            const ulonglong2* p = (const ulonglong2*)(w_ih + rows[g] * DD);
            #pragma unroll
            for (int j = 0; j < DD / 4; j++) wv[g][j] = p[j];
        }
    }
    const float br = b_ih[u]          + b_hh[u];
    const float bz = b_ih[HH + u]     + b_hh[HH + u];
    const float bn = b_ih[2 * HH + u];

    for (int i = tid; i < PT * DD / 4; i += 128)
        ((float4*)&xs[0][0])[i] =
            ((const float4*)(x + ((size_t)b * TT + t0) * DD))[i];
    __syncthreads();

    #pragma unroll 4
    for (int k = 0; k < PT / 2; k++) {
        const int tt = th * (PT / 2) + k;
        const ulonglong2* xp = (const ulonglong2*)xs[tt];
        ull a0 = 0ull, a1 = 0ull, a2 = 0ull;
        #pragma unroll
        for (int j = 0; j < DD / 4; j++) {
            ulonglong2 xv = xp[j];
            a0 = fma2(wv[0][j].x, xv.x, a0);
            a0 = fma2(wv[0][j].y, xv.y, a0);
            a1 = fma2(wv[1][j].x, xv.x, a1);
            a1 = fma2(wv[1][j].y, xv.y, a1);
            a2 = fma2(wv[2][j].x, xv.x, a2);
            a2 = fma2(wv[2][j].y, xv.y, a2);
        }
        __half2 rz = __floats2half2_rn(hadd2(a0) + br, hadd2(a1) + bz);
        __half2 n0 = __floats2half2_rn(hadd2(a2) + bn, 0.f);
        uint2 pkt;
        pkt.x = *reinterpret_cast<unsigned*>(&rz);
        pkt.y = *reinterpret_cast<unsigned*>(&n0);
        *reinterpret_cast<uint2*>(g_xg + ((size_t)(b * TT + t0 + tt) * 256) + u * 4) = pkt;
    }
}

// ---------------------------------------------------------------------------
// Kernel 2: forward recurrence, k-split-2. Grid 512 (all CTAs wave-1 resident
// at occ 4 => 3.46 warps/SMSP on ALL SMSPs). CTA = 128 thr = 1 row; thread
// (u, kh) owns unit u's 3 gate half-rows over k in [32kh, 32kh+32) — 96
// weight regs. Partials exchanged packed (f32x2) via SMEM + __syncthreads;
// BOTH halves finalize redundantly (commutative adds -> identical h) and keep
// a per-kh h copy, so h visibility needs only a 64-thread named barrier.
// ---------------------------------------------------------------------------
__global__ __launch_bounds__(128, 4)
void gru_rec_kernel(const float* __restrict__ w_hh,
                    const float* __restrict__ b_hh,
                    const float* __restrict__ x,
                    const float* __restrict__ w_ih_b,
                    const float* __restrict__ b_ih_b,
                    const float* __restrict__ b_hh_b,
                    const float* __restrict__ fc_w,
                    const float* __restrict__ fc_b,
                    float* __restrict__ out)
{
    __shared__ __align__(16) float h2[2][2][HH];        // [kh][parity][unit]
    __shared__ __align__(16) ull part_sh[2][2][3][HH];  // [parity][kh][gate][unit]
    __shared__ __align__(16) __half xg_sh[2][BK * 256]; // 2 x 8KB
    __shared__ float red_sh[HH];

    const int tid = threadIdx.x;
    const int u   = tid & 63;
    const int kh  = tid >> 6;        // warps {0,1}=kh0, {2,3}=kh1 -> SMSP 0..3
    const int b   = blockIdx.x;

    // half-rows r(u), z(u), n(u) of w_hh, cols [32kh, 32kh+32): 24 ulonglong2
    ulonglong2 w[3][8];
    {
        const int rows[3] = { u, HH + u, 2 * HH + u };
        #pragma unroll
        for (int i = 0; i < 3; i++) {
            const ulonglong2* p = (const ulonglong2*)(w_hh + rows[i] * HH + 32 * kh);
            #pragma unroll
            for (int j = 0; j < 8; j++) w[i][j] = p[j];
        }
    }
    const float bhn = b_hh[2 * HH + u];

    const char* xg_g = (const char*)(g_xg + (size_t)b * TT * 256);
    const unsigned xg_sb = (unsigned)__cvta_generic_to_shared(&xg_sh[0][0]);
    // per block: 8192 B = 512 x 16B chunks; 4 per thread

    float hold = 0.f;
    h2[kh][0][u] = 0.f;

    // prologue: stage block 0 into buffer 0
    #pragma unroll
    for (int c = 0; c < 4; c++)
        cpa16(xg_sb + (tid + 128 * c) * 16, xg_g + (tid + 128 * c) * 16);
    cpa_commit();
    __syncthreads();

    int p = 0;
    for (int blk = 0; blk < NBK; ++blk) {
        if (blk + 1 < NBK) {
            unsigned dst = xg_sb + ((blk & 1) ? 0u : (unsigned)XGBB);
            const char* src = xg_g + (size_t)(blk + 1) * XGBB;
            #pragma unroll
            for (int c = 0; c < 4; c++)
                cpa16(dst + (tid + 128 * c) * 16, src + (tid + 128 * c) * 16);
        }
        cpa_commit();
        cpa_wait1();
        __syncthreads();

        const __half* xb = &xg_sh[blk & 1][0];

        #pragma unroll 4
        for (int tt = 0; tt < BK; ++tt) {
            // xg packet for unit u (both kh load same -> broadcast LDS.64)
            uint2 pkt = *reinterpret_cast<const uint2*>(xb + tt * 256 + u * 4);
            float2 rzx = __half22float2(*reinterpret_cast<__half2*>(&pkt.x));
            float  xn  = __half2float(*reinterpret_cast<__half*>(&pkt.y));

            // half-dots over own k-range (h segment is broadcast across warp)
            const ulonglong2* hp = (const ulonglong2*)&h2[kh][p][32 * kh];
            ull a0 = 0ull, a1 = 0ull, a2 = 0ull;
            #pragma unroll
            for (int j = 0; j < 8; j++) {
                ulonglong2 hv = hp[j];
                a0 = fma2(w[0][j].x, hv.x, a0); a0 = fma2(w[0][j].y, hv.y, a0);
                a1 = fma2(w[1][j].x, hv.x, a1); a1 = fma2(w[1][j].y, hv.y, a1);
                a2 = fma2(w[2][j].x, hv.x, a2); a2 = fma2(w[2][j].y, hv.y, a2);
            }

            part_sh[p][kh][0][u] = a0;
            part_sh[p][kh][1][u] = a1;
            part_sh[p][kh][2][u] = a2;
            __syncthreads();

            // redundant finalize on both halves (identical results)
            ull o0 = part_sh[p][kh ^ 1][0][u];
            ull o1 = part_sh[p][kh ^ 1][1][u];
            ull o2 = part_sh[p][kh ^ 1][2][u];
            float rr = siga(rzx.x + hadd2(addf2(a0, o0)));
            float zz = siga(rzx.y + hadd2(addf2(a1, o1)));
            float nn = tanha(fmaf(rr, hadd2(addf2(a2, o2)) + bhn, xn));
            hold = fmaf(zz, hold - nn, nn);

            h2[kh][p ^ 1][u] = hold;       // own-group h copy
            bargrp(1 + kh);                // 64-thread group barrier
            p ^= 1;
        }
    }
    __syncthreads();

    // ---- epilogue: backward GRU = ONE step from h=0 on x[:,T-1,:]; then fc ----
    if (kh == 0) {
        const int j = u;
        const float* xl = x + ((size_t)b * TT + (TT - 1)) * DD;
        float xv[DD];
        #pragma unroll
        for (int k = 0; k < DD; k++) xv[k] = __ldg(xl + k);

        float ar  = __ldg(b_ih_b + j)          + __ldg(b_hh_b + j);
        float az  = __ldg(b_ih_b + HH + j)     + __ldg(b_hh_b + HH + j);
        float anx = __ldg(b_ih_b + 2 * HH + j);
        float anh = __ldg(b_hh_b + 2 * HH + j);
        const float* wr = w_ih_b + (size_t)j * DD;
        const float* wz = w_ih_b + (size_t)(HH + j) * DD;
        const float* wn = w_ih_b + (size_t)(2 * HH + j) * DD;
        #pragma unroll
        for (int k = 0; k < DD; k++) {
            ar  += __ldg(wr + k) * xv[k];
            az  += __ldg(wz + k) * xv[k];
            anx += __ldg(wn + k) * xv[k];
        }
        float rb = siga(ar);
        float zb = siga(az);
        float nb = tanha(anx + rb * anh);
        float hb = (1.f - zb) * nb;            // h_prev = 0

        red_sh[j] = hold * __ldg(fc_w + j) + hb * __ldg(fc_w + HH + j);
    }
    __syncthreads();
    if (tid == 0) {
        float sum = __ldg(fc_b);
        #pragma unroll
        for (int k = 0; k < HH; k++) sum += red_sh[k];
        out[b] = sum;
    }
}

extern "C" void kernel_launch(void* const* d_in, const int* in_sizes, int n_in,
                              void* d_out, int out_size)
{
    const float* x      = (const float*)d_in[0];
    const float* w_ih_f = (const float*)d_in[1];
    const float* w_hh_f = (const float*)d_in[2];
    const float* b_ih_f = (const float*)d_in[3];
    const float* b_hh_f = (const float*)d_in[4];
    const float* w_ih_b = (const float*)d_in[5];
    /* d_in[6] = w_hh_b unused: backward direction starts from h=0 */
    const float* b_ih_b = (const float*)d_in[7];
    const float* b_hh_b = (const float*)d_in[8];
    const float* fc_w   = (const float*)d_in[9];
    const float* fc_b   = (const float*)d_in[10];

    xg_kernel<<<dim3(TT / PT, BB), 128>>>(x, w_ih_f, b_ih_f, b_hh_f);
    gru_rec_kernel<<<BB, 128>>>(w_hh_f, b_hh_f, x,
                                w_ih_b, b_ih_b, b_hh_b,
                                fc_w, fc_b, (float*)d_out);
}

// round 13
// speedup vs baseline: 1.9811x; 1.2374x over previous
#include <cuda_runtime.h>
#include <cuda_fp16.h>

#define TT 512
#define BB 512
#define DD 16
#define HH 64
#define PT 64          // timesteps per precompute CTA
#define BK 16          // timesteps per staged xg block in rec kernel
#define NBK (TT / BK)
#define XGBB (BK * 256 * 2)   // bytes per staged block = 8192

typedef unsigned long long ull;

__device__ __forceinline__ ull fma2(ull a, ull b, ull c) {
    ull d;
    asm("fma.rn.f32x2 %0, %1, %2, %3;" : "=l"(d) : "l"(a), "l"(b), "l"(c));
    return d;
}
__device__ __forceinline__ ull addf2(ull a, ull b) {
    ull d;
    asm("add.rn.f32x2 %0, %1, %2;" : "=l"(d) : "l"(a), "l"(b));
    return d;
}
__device__ __forceinline__ float hadd2(ull a) {
    return __uint_as_float((unsigned)a) + __uint_as_float((unsigned)(a >> 32));
}
__device__ __forceinline__ float tanha(float x) {
    float y;
    asm("tanh.approx.f32 %0, %1;" : "=f"(y) : "f"(x));
    return y;
}
__device__ __forceinline__ float siga(float x) {
    return fmaf(0.5f, tanha(0.5f * x), 0.5f);
}
__device__ __forceinline__ void cpa16(unsigned smem, const void* gmem) {
    asm volatile("cp.async.ca.shared.global [%0], [%1], 16;\n"
                 :: "r"(smem), "l"(gmem));
}
__device__ __forceinline__ void cpa_commit() {
    asm volatile("cp.async.commit_group;\n" ::: "memory");
}
__device__ __forceinline__ void cpa_wait1() {
    asm volatile("cp.async.wait_group 1;\n" ::: "memory");
}

// scratch: xg[b][t][u][{r,z,n,pad}] fp16; r,z include b_ih+b_hh, n includes b_ih
__device__ __half g_xg[(size_t)BB * TT * 256];

// ---------------------------------------------------------------------------
// Kernel 1: xg precompute (R10-proven). thread = (unit u, t-half); all 3
// gates per unit (x loads amortized); packed {r,z,n,0} 8-byte store.
// ---------------------------------------------------------------------------
__global__ __launch_bounds__(128)
void xg_kernel(const float* __restrict__ x,
               const float* __restrict__ w_ih,
               const float* __restrict__ b_ih,
               const float* __restrict__ b_hh)
{
    __shared__ __align__(16) float xs[PT][DD];
    const int tid = threadIdx.x;
    const int u   = tid & 63;
    const int th  = tid >> 6;
    const int b   = blockIdx.y;
    const int t0  = blockIdx.x * PT;

    ulonglong2 wv[3][DD / 4];
    {
        const int rows[3] = { u, HH + u, 2 * HH + u };
        #pragma unroll
        for (int g = 0; g < 3; g++) {
            const ulonglong2* p = (const ulonglong2*)(w_ih + rows[g] * DD);
            #pragma unroll
            for (int j = 0; j < DD / 4; j++) wv[g][j] = p[j];
        }
    }
    const float br = b_ih[u]          + b_hh[u];
    const float bz = b_ih[HH + u]     + b_hh[HH + u];
    const float bn = b_ih[2 * HH + u];

    for (int i = tid; i < PT * DD / 4; i += 128)
        ((float4*)&xs[0][0])[i] =
            ((const float4*)(x + ((size_t)b * TT + t0) * DD))[i];
    __syncthreads();

    #pragma unroll 4
    for (int k = 0; k < PT / 2; k++) {
        const int tt = th * (PT / 2) + k;
        const ulonglong2* xp = (const ulonglong2*)xs[tt];
        ull a0 = 0ull, a1 = 0ull, a2 = 0ull;
        #pragma unroll
        for (int j = 0; j < DD / 4; j++) {
            ulonglong2 xv = xp[j];
            a0 = fma2(wv[0][j].x, xv.x, a0);
            a0 = fma2(wv[0][j].y, xv.y, a0);
            a1 = fma2(wv[1][j].x, xv.x, a1);
            a1 = fma2(wv[1][j].y, xv.y, a1);
            a2 = fma2(wv[2][j].x, xv.x, a2);
            a2 = fma2(wv[2][j].y, xv.y, a2);
        }
        __half2 rz = __floats2half2_rn(hadd2(a0) + br, hadd2(a1) + bz);
        __half2 n0 = __floats2half2_rn(hadd2(a2) + bn, 0.f);
        uint2 pkt;
        pkt.x = *reinterpret_cast<unsigned*>(&rz);
        pkt.y = *reinterpret_cast<unsigned*>(&n0);
        *reinterpret_cast<uint2*>(g_xg + ((size_t)(b * TT + t0 + tt) * 256) + u * 4) = pkt;
    }
}

// ---------------------------------------------------------------------------
// Kernel 2: forward recurrence (R6 architecture, best measured). Grid 512,
// CTA = 64 threads = 1 row; 3.46 CTAs/SM overlap on SMSP {0,1} — cross-CTA
// overlap hides the serial tail (R6: 8 cyc exposed). Thread owns unit u
// completely (192 weight regs, full 64-wide dots); ONE __syncthreads per
// step; xg consumed as packed {r,z,n} via a single LDS.64.
// ---------------------------------------------------------------------------
__global__ __launch_bounds__(64, 4)
void gru_rec_kernel(const float* __restrict__ w_hh,
                    const float* __restrict__ b_hh,
                    const float* __restrict__ x,
                    const float* __restrict__ w_ih_b,
                    const float* __restrict__ b_ih_b,
                    const float* __restrict__ b_hh_b,
                    const float* __restrict__ fc_w,
                    const float* __restrict__ fc_b,
                    float* __restrict__ out)
{
    __shared__ __align__(16) float h_sh[2][HH];
    __shared__ __align__(16) __half xg_sh[2][BK * 256];   // 2 x 8KB
    __shared__ float red_sh[HH];

    const int u = threadIdx.x;       // unit 0..63
    const int b = blockIdx.x;

    // full rows r(u), z(u), n(u) of w_hh: 3 x 64 floats = 48 ulonglong2
    ulonglong2 w[3][16];
    {
        const int rows[3] = { u, HH + u, 2 * HH + u };
        #pragma unroll
        for (int i = 0; i < 3; i++) {
            const ulonglong2* p = (const ulonglong2*)(w_hh + rows[i] * HH);
            #pragma unroll
            for (int j = 0; j < 16; j++) w[i][j] = p[j];
        }
    }
    const float bhn = b_hh[2 * HH + u];

    const char* xg_g = (const char*)(g_xg + (size_t)b * TT * 256);
    const unsigned xg_sb = (unsigned)__cvta_generic_to_shared(&xg_sh[0][0]);
    // per block: 8192 B = 512 x 16B chunks; 8 per thread

    float hold = 0.f;
    h_sh[0][u] = 0.f;

    // prologue: stage block 0 into buffer 0
    #pragma unroll
    for (int c = 0; c < 8; c++)
        cpa16(xg_sb + (u + 64 * c) * 16, xg_g + (u + 64 * c) * 16);
    cpa_commit();
    __syncthreads();

    int p = 0;
    for (int blk = 0; blk < NBK; ++blk) {
        if (blk + 1 < NBK) {
            unsigned dst = xg_sb + ((blk & 1) ? 0u : (unsigned)XGBB);
            const char* src = xg_g + (size_t)(blk + 1) * XGBB;
            #pragma unroll
            for (int c = 0; c < 8; c++)
                cpa16(dst + (u + 64 * c) * 16, src + (u + 64 * c) * 16);
        }
        cpa_commit();
        cpa_wait1();
        __syncthreads();

        const __half* xb = &xg_sh[blk & 1][0];

        #pragma unroll 4
        for (int tt = 0; tt < BK; ++tt) {
            // packed xg for this unit/step: one LDS.64
            uint2 pkt = *reinterpret_cast<const uint2*>(xb + tt * 256 + u * 4);
            float2 rzx = __half22float2(*reinterpret_cast<__half2*>(&pkt.x));
            float  xn  = __half2float(*reinterpret_cast<__half*>(&pkt.y));

            const ulonglong2* hp = (const ulonglong2*)&h_sh[p][0];
            ull a0 = 0ull, a1 = 0ull, a2 = 0ull;
            ull c0 = 0ull, c1 = 0ull, c2 = 0ull;
            #pragma unroll
            for (int j = 0; j < 8; j++) {
                ulonglong2 hv = hp[j];
                a0 = fma2(w[0][j].x, hv.x, a0); a0 = fma2(w[0][j].y, hv.y, a0);
                a1 = fma2(w[1][j].x, hv.x, a1); a1 = fma2(w[1][j].y, hv.y, a1);
                a2 = fma2(w[2][j].x, hv.x, a2); a2 = fma2(w[2][j].y, hv.y, a2);
            }
            #pragma unroll
            for (int j = 8; j < 16; j++) {
                ulonglong2 hv = hp[j];
                c0 = fma2(w[0][j].x, hv.x, c0); c0 = fma2(w[0][j].y, hv.y, c0);
                c1 = fma2(w[1][j].x, hv.x, c1); c1 = fma2(w[1][j].y, hv.y, c1);
                c2 = fma2(w[2][j].x, hv.x, c2); c2 = fma2(w[2][j].y, hv.y, c2);
            }

            float rr = siga(rzx.x + hadd2(addf2(a0, c0)));
            float zz = siga(rzx.y + hadd2(addf2(a1, c1)));
            float nn = tanha(fmaf(rr, hadd2(addf2(a2, c2)) + bhn, xn));
            hold = fmaf(zz, hold - nn, nn);     // (1-z)n + z h

            h_sh[p ^ 1][u] = hold;
            __syncthreads();
            p ^= 1;
        }
    }

    // ---- epilogue: backward GRU = ONE step from h=0 on x[:,T-1,:]; then fc ----
    {
        const int j = u;
        const float* xl = x + ((size_t)b * TT + (TT - 1)) * DD;
        float xv[DD];
        #pragma unroll
        for (int k = 0; k < DD; k++) xv[k] = __ldg(xl + k);

        float ar  = __ldg(b_ih_b + j)          + __ldg(b_hh_b + j);
        float az  = __ldg(b_ih_b + HH + j)     + __ldg(b_hh_b + HH + j);
        float anx = __ldg(b_ih_b + 2 * HH + j);
        float anh = __ldg(b_hh_b + 2 * HH + j);
        const float* wr = w_ih_b + (size_t)j * DD;
        const float* wz = w_ih_b + (size_t)(HH + j) * DD;
        const float* wn = w_ih_b + (size_t)(2 * HH + j) * DD;
        #pragma unroll
        for (int k = 0; k < DD; k++) {
            ar  += __ldg(wr + k) * xv[k];
            az  += __ldg(wz + k) * xv[k];
            anx += __ldg(wn + k) * xv[k];
        }
        float rb = siga(ar);
        float zb = siga(az);
        float nb = tanha(anx + rb * anh);
        float hb = (1.f - zb) * nb;            // h_prev = 0

        red_sh[j] = hold * __ldg(fc_w + j) + hb * __ldg(fc_w + HH + j);
    }
    __syncthreads();
    if (u == 0) {
        float sum = __ldg(fc_b);
        #pragma unroll
        for (int k = 0; k < HH; k++) sum += red_sh[k];
        out[b] = sum;
    }
}

extern "C" void kernel_launch(void* const* d_in, const int* in_sizes, int n_in,
                              void* d_out, int out_size)
{
    const float* x      = (const float*)d_in[0];
    const float* w_ih_f = (const float*)d_in[1];
    const float* w_hh_f = (const float*)d_in[2];
    const float* b_ih_f = (const float*)d_in[3];
    const float* b_hh_f = (const float*)d_in[4];
    const float* w_ih_b = (const float*)d_in[5];
    /* d_in[6] = w_hh_b unused: backward direction starts from h=0 */
    const float* b_ih_b = (const float*)d_in[7];
    const float* b_hh_b = (const float*)d_in[8];
    const float* fc_w   = (const float*)d_in[9];
    const float* fc_b   = (const float*)d_in[10];

    xg_kernel<<<dim3(TT / PT, BB), 128>>>(x, w_ih_f, b_ih_f, b_hh_f);
    gru_rec_kernel<<<BB, 64>>>(w_hh_f, b_hh_f, x,
                               w_ih_b, b_ih_b, b_hh_b,
                               fc_w, fc_b, (float*)d_out);
}